// round 5
// baseline (speedup 1.0000x reference)
#include <cuda_runtime.h>
#include <cuda_bf16.h>
#include <math.h>

// Problem dims (fixed by setup_inputs)
#define BB 64
#define KK 8
#define FF 24
#define DD 32   // KK + FF
#define HH 64
#define LL 2048
#define CC 64
#define XAUG_ELEMS (BB * LL * CC)   // 8388608

#define TPB   256                         // threads per block
#define ITERS 4                           // float4 per thread
#define V4_PER_BATCH (LL * CC / 4)        // 32768
#define V4_PER_BLOCK (TPB * ITERS)        // 1024
#define BPB (V4_PER_BATCH / V4_PER_BLOCK) // 32 blocks per batch

// ---------------------------------------------------------------------------
// Single fused kernel, MLP-FIRST ordering (R3 post-mortem: the L1tex queue is
// a single in-order FIFO, so bulk x-prefetch ahead of the MLP serializes the
// whole block; weight loads must be issued first).
//  - Warps 0-3 (threads 0-127): dual MLP (prob on 0-63, intensity on 64-127).
//    Weights are L1-resident after the first block on each SM.
//  - Warps 4-7 (threads 128-255): prefetch THEIR half of x concurrently —
//    issue-interleaved with weight loads, hides half the stream latency.
//  - Selection is exactly one-hot (y_soft - stop_grad(y_soft) == 0), so only
//    the selected transform is applied. k==7 flip is done on the store side,
//    so load addresses are k-independent.
//  - blockIdx.x==0 blocks write the small tail outputs (prob/intensity/sel).
// ---------------------------------------------------------------------------
__global__ void __launch_bounds__(TPB) fused_kernel(
    const float* __restrict__ x,
    const float* __restrict__ prev_prob,   // (B,K)
    const float* __restrict__ features,    // (B,F)
    const float* __restrict__ gumbel,      // (B,K)
    const float* __restrict__ pW1, const float* __restrict__ pb1,
    const float* __restrict__ pW2, const float* __restrict__ pb2,
    const float* __restrict__ pW3, const float* __restrict__ pb3,
    const float* __restrict__ iW1, const float* __restrict__ ib1,
    const float* __restrict__ iW2, const float* __restrict__ ib2,
    const float* __restrict__ iW3, const float* __restrict__ ib3,
    float* __restrict__ out,
    float* __restrict__ out_prob,          // (B,K)
    float* __restrict__ out_int,           // (B,K)
    float* __restrict__ out_sel)           // (B,)
{
    const int b   = blockIdx.y;
    const int tid = threadIdx.x;

    __shared__ float s_in[DD];
    __shared__ float hp1[HH], hp2[HH];     // prob MLP hiddens
    __shared__ float hi1[HH], hi2[HH];     // intensity MLP hiddens
    __shared__ float s_logit[KK];
    __shared__ float s_int[KK];
    __shared__ int   s_ki;
    __shared__ float s_t;

    const float4* __restrict__ xi = (const float4*)(x + (size_t)b * LL * CC);
    const int base = blockIdx.x * V4_PER_BLOCK + tid;

    // Stage MLP input (warp 0 only — issues before/with weight loads)
    if (tid < KK)       s_in[tid] = prev_prob[b * KK + tid];
    else if (tid < DD)  s_in[tid] = features[b * FF + (tid - KK)];

    // Warps 4-7 prefetch their x while the MLP runs on warps 0-3.
    float4 v[ITERS];
    if (tid >= 128) {
        #pragma unroll
        for (int j = 0; j < ITERS; j++) v[j] = xi[base + j * TPB];
    }
    __syncthreads();

    // ---- two MLPs in parallel: threads 0-63 prob, 64-127 intensity ----
    const int  lt  = tid & 63;
    const bool isP = (tid < 64);
    const bool act = (tid < 128);

    if (act) {
        const float* W1 = isP ? pW1 : iW1;  const float* b1 = isP ? pb1 : ib1;
        float* h1 = isP ? hp1 : hi1;
        float a = b1[lt];
        #pragma unroll
        for (int i = 0; i < DD; i++) a = fmaf(s_in[i], W1[i * HH + lt], a);
        h1[lt] = fmaxf(a, 0.f);
    }
    __syncthreads();
    if (act) {
        const float* W2 = isP ? pW2 : iW2;  const float* b2 = isP ? pb2 : ib2;
        const float* h1 = isP ? hp1 : hi1;  float* h2 = isP ? hp2 : hi2;
        float a = b2[lt];
        #pragma unroll 16
        for (int i = 0; i < HH; i++) a = fmaf(h1[i], W2[i * HH + lt], a);
        h2[lt] = fmaxf(a, 0.f);
    }
    __syncthreads();
    if (act && lt < KK) {
        const float* W3 = isP ? pW3 : iW3;  const float* b3 = isP ? pb3 : ib3;
        const float* h2 = isP ? hp2 : hi2;
        float a = b3[lt];
        #pragma unroll 16
        for (int i = 0; i < HH; i++) a = fmaf(h2[i], W3[i * KK + lt], a);
        if (isP) s_logit[lt] = a;
        else     s_int[lt]   = (a > 20.f) ? a : log1pf(expf(a));  // softplus
    }
    __syncthreads();

    if (tid == 0) {
        // argmax(logits + gumbel) == argmax(y_soft); selection is exactly one-hot
        int best = 0;
        float bv = s_logit[0] + gumbel[b * KK + 0];
        #pragma unroll
        for (int k = 1; k < KK; k++) {
            float t2 = s_logit[k] + gumbel[b * KK + k];
            if (t2 > bv) { bv = t2; best = k; }
        }
        s_ki = best;
        s_t  = s_int[best];

        if (blockIdx.x == 0) {
            // softmax over K=8 logits
            float m = s_logit[0];
            #pragma unroll
            for (int k = 1; k < KK; k++) m = fmaxf(m, s_logit[k]);
            float e[KK]; float sum = 0.f;
            #pragma unroll
            for (int k = 0; k < KK; k++) { e[k] = expf(s_logit[k] - m); sum += e[k]; }
            float inv = 1.f / sum;
            #pragma unroll
            for (int k = 0; k < KK; k++) out_prob[b * KK + k] = e[k] * inv;
            #pragma unroll
            for (int k = 0; k < KK; k++) out_int[b * KK + k] = s_int[k];
            out_sel[b] = (float)best;
        }
    }
    __syncthreads();

    // Remaining half of the loads (threads 0-127)
    if (tid < 128) {
        #pragma unroll
        for (int j = 0; j < ITERS; j++) v[j] = xi[base + j * TPB];
    }

    const int   k = s_ki;
    const float t = s_t;
    float4* __restrict__ oo = (float4*)(out + (size_t)b * LL * CC);

    if (k == 7) {
        // time reversal: identity values, flipped store position (coalesced)
        #pragma unroll
        for (int j = 0; j < ITERS; j++) {
            int idx = base + j * TPB;
            int l   = idx >> 4;
            int c4  = idx & 15;
            oo[((LL - 1 - l) << 4) + c4] = v[j];
        }
    } else if (k == 4) {
        const float A = 1.f + t;
        #pragma unroll
        for (int j = 0; j < ITERS; j++) {
            float4 w = v[j];
            w.x = tanhf(w.x * A); w.y = tanhf(w.y * A);
            w.z = tanhf(w.z * A); w.w = tanhf(w.w * A);
            oo[base + j * TPB] = w;
        }
    } else if (k == 6) {
        #pragma unroll
        for (int j = 0; j < ITERS; j++) {
            float4 w = v[j];
            w.x = fmaf(t, sinf(w.x), w.x); w.y = fmaf(t, sinf(w.y), w.y);
            w.z = fmaf(t, sinf(w.z), w.z); w.w = fmaf(t, sinf(w.w), w.w);
            oo[base + j * TPB] = w;
        }
    } else {
        // k in {0,1,2,3,5}: affine A*x + Bc
        float A = 1.f, Bc = 0.f;
        if      (k == 1) A = 1.f + t;
        else if (k == 2) Bc = t;
        else if (k == 3) A = 1.f - t;
        else if (k == 5) A = expf(-t);
        #pragma unroll
        for (int j = 0; j < ITERS; j++) {
            float4 w = v[j];
            w.x = fmaf(w.x, A, Bc); w.y = fmaf(w.y, A, Bc);
            w.z = fmaf(w.z, A, Bc); w.w = fmaf(w.w, A, Bc);
            oo[base + j * TPB] = w;
        }
    }
}

extern "C" void kernel_launch(void* const* d_in, const int* in_sizes, int n_in,
                              void* d_out, int out_size)
{
    const float* x         = (const float*)d_in[0];
    const float* prev_prob = (const float*)d_in[1];
    const float* features  = (const float*)d_in[2];
    const float* gumbel    = (const float*)d_in[3];
    // d_in[4] = log_temperature: dead for forward values (exact one-hot selection;
    // tau>0 never changes the argmax; prob uses the raw softmax of logits).
    const float* pW1 = (const float*)d_in[5];
    const float* pb1 = (const float*)d_in[6];
    const float* pW2 = (const float*)d_in[7];
    const float* pb2 = (const float*)d_in[8];
    const float* pW3 = (const float*)d_in[9];
    const float* pb3 = (const float*)d_in[10];
    const float* iW1 = (const float*)d_in[11];
    const float* ib1 = (const float*)d_in[12];
    const float* iW2 = (const float*)d_in[13];
    const float* ib2 = (const float*)d_in[14];
    const float* iW3 = (const float*)d_in[15];
    const float* ib3 = (const float*)d_in[16];

    float* out      = (float*)d_out;
    float* out_prob = out + XAUG_ELEMS;              // (B,K)
    float* out_int  = out_prob + BB * KK;            // (B,K)
    float* out_sel  = out_int  + BB * KK;            // (B,)

    dim3 grid(BPB, BB);   // (32, 64) = 2048 blocks
    fused_kernel<<<grid, TPB>>>(x, prev_prob, features, gumbel,
                                pW1, pb1, pW2, pb2, pW3, pb3,
                                iW1, ib1, iW2, ib2, iW3, ib3,
                                out, out_prob, out_int, out_sel);
}

// round 6
// speedup vs baseline: 1.2040x; 1.2040x over previous
#include <cuda_runtime.h>
#include <cuda_bf16.h>
#include <math.h>

// Problem dims (fixed by setup_inputs)
#define BB 64
#define KK 8
#define FF 24
#define DD 32   // KK + FF
#define HH 64
#define LL 2048
#define CC 64
#define XAUG_ELEMS (BB * LL * CC)   // 8388608

// Per-batch selected transform + its intensity (scratch; no allocation allowed)
__device__ int   g_sel_k[BB];
__device__ float g_sel_t[BB];

// ---------------------------------------------------------------------------
// Kernel 1: per-batch MLPs (prob + intensity), softmax, argmax(logits+gumbel).
// One block per batch, 64 threads. Triggers the dependent apply kernel as soon
// as its writes are done (PDL).
// ---------------------------------------------------------------------------
__global__ void setup_kernel(
    const float* __restrict__ prev_prob,   // (B,K)
    const float* __restrict__ features,    // (B,F)
    const float* __restrict__ gumbel,      // (B,K)
    const float* __restrict__ pW1, const float* __restrict__ pb1,
    const float* __restrict__ pW2, const float* __restrict__ pb2,
    const float* __restrict__ pW3, const float* __restrict__ pb3,
    const float* __restrict__ iW1, const float* __restrict__ ib1,
    const float* __restrict__ iW2, const float* __restrict__ ib2,
    const float* __restrict__ iW3, const float* __restrict__ ib3,
    float* __restrict__ out_prob,          // (B,K)
    float* __restrict__ out_int,           // (B,K)
    float* __restrict__ out_sel)           // (B,)
{
    const int b   = blockIdx.x;
    const int tid = threadIdx.x;           // 0..63

    __shared__ float s_in[DD];
    __shared__ float h1[HH];
    __shared__ float h2[HH];
    __shared__ float s_logit[KK];
    __shared__ float s_int[KK];

    if (tid < KK)       s_in[tid] = prev_prob[b * KK + tid];
    else if (tid < DD)  s_in[tid] = features[b * FF + (tid - KK)];
    __syncthreads();

    // ---------- prob MLP ----------
    {
        float a = pb1[tid];
        #pragma unroll
        for (int i = 0; i < DD; i++) a = fmaf(s_in[i], pW1[i * HH + tid], a);
        h1[tid] = fmaxf(a, 0.f);
    }
    __syncthreads();
    {
        float a = pb2[tid];
        #pragma unroll 16
        for (int i = 0; i < HH; i++) a = fmaf(h1[i], pW2[i * HH + tid], a);
        h2[tid] = fmaxf(a, 0.f);
    }
    __syncthreads();
    if (tid < KK) {
        float a = pb3[tid];
        #pragma unroll 16
        for (int i = 0; i < HH; i++) a = fmaf(h2[i], pW3[i * KK + tid], a);
        s_logit[tid] = a;
    }
    __syncthreads();   // h1/h2 reads done before reuse

    // ---------- intensity MLP ----------
    {
        float a = ib1[tid];
        #pragma unroll
        for (int i = 0; i < DD; i++) a = fmaf(s_in[i], iW1[i * HH + tid], a);
        h1[tid] = fmaxf(a, 0.f);
    }
    __syncthreads();
    {
        float a = ib2[tid];
        #pragma unroll 16
        for (int i = 0; i < HH; i++) a = fmaf(h1[i], iW2[i * HH + tid], a);
        h2[tid] = fmaxf(a, 0.f);
    }
    __syncthreads();
    if (tid < KK) {
        float a = ib3[tid];
        #pragma unroll 16
        for (int i = 0; i < HH; i++) a = fmaf(h2[i], iW3[i * KK + tid], a);
        s_int[tid] = (a > 20.f) ? a : log1pf(expf(a));   // stable softplus
    }
    __syncthreads();

    if (tid == 0) {
        // softmax over K=8 logits
        float m = s_logit[0];
        #pragma unroll
        for (int k = 1; k < KK; k++) m = fmaxf(m, s_logit[k]);
        float e[KK]; float sum = 0.f;
        #pragma unroll
        for (int k = 0; k < KK; k++) { e[k] = expf(s_logit[k] - m); sum += e[k]; }
        float inv = 1.f / sum;
        #pragma unroll
        for (int k = 0; k < KK; k++) out_prob[b * KK + k] = e[k] * inv;

        // argmax(logits + gumbel) == argmax(y_soft); selection is exactly one-hot
        // (y_hard + y_soft - stop_grad(y_soft) == y_hard numerically).
        int best = 0;
        float bv = s_logit[0] + gumbel[b * KK + 0];
        #pragma unroll
        for (int k = 1; k < KK; k++) {
            float v = s_logit[k] + gumbel[b * KK + k];
            if (v > bv) { bv = v; best = k; }
        }
        #pragma unroll
        for (int k = 0; k < KK; k++) out_int[b * KK + k] = s_int[k];
        out_sel[b] = (float)best;
        g_sel_k[b] = best;
        g_sel_t[b] = s_int[best];
    }
    __syncthreads();
#if __CUDA_ARCH__ >= 900
    // Release the dependent apply kernel; this CTA's prior writes become
    // visible to it after its cudaGridDependencySynchronize().
    cudaTriggerProgrammaticLaunchCompletion();
#endif
}

// ---------------------------------------------------------------------------
// Kernel 2: apply the single selected transform per batch (R2 structure —
// proven 13.4us). Front-issues the k-independent x loads, then waits on the
// PDL dependency before reading the selection.
// grid = (32, B), 256 threads, 4 float4 per thread.
// ---------------------------------------------------------------------------
__global__ void __launch_bounds__(256) apply_kernel(
    const float* __restrict__ x, float* __restrict__ out)
{
    const int b = blockIdx.y;

    const float4* __restrict__ xi = (const float4*)(x   + (size_t)b * LL * CC);
    float4*       __restrict__ oo = (float4*)      (out + (size_t)b * LL * CC);

    const int base = blockIdx.x * 1024 + threadIdx.x;   // 32 blocks * 1024 = 32768

    // k-independent loads (k==7 flip is applied on the store side)
    float4 v[4];
    #pragma unroll
    for (int j = 0; j < 4; j++) v[j] = xi[base + j * 256];

#if __CUDA_ARCH__ >= 900
    cudaGridDependencySynchronize();   // wait for setup's trigger; makes g_sel visible
#endif
    const int   k = g_sel_k[b];
    const float t = g_sel_t[b];

    if (k == 7) {
        // time reversal: identity values, flipped (still coalesced) store position
        #pragma unroll
        for (int j = 0; j < 4; j++) {
            int idx = base + j * 256;
            int l   = idx >> 4;
            int c4  = idx & 15;
            oo[((LL - 1 - l) << 4) + c4] = v[j];
        }
    } else if (k == 4) {
        const float A = 1.f + t;
        #pragma unroll
        for (int j = 0; j < 4; j++) {
            float4 w = v[j];
            w.x = tanhf(w.x * A); w.y = tanhf(w.y * A);
            w.z = tanhf(w.z * A); w.w = tanhf(w.w * A);
            oo[base + j * 256] = w;
        }
    } else if (k == 6) {
        #pragma unroll
        for (int j = 0; j < 4; j++) {
            float4 w = v[j];
            w.x = fmaf(t, sinf(w.x), w.x); w.y = fmaf(t, sinf(w.y), w.y);
            w.z = fmaf(t, sinf(w.z), w.z); w.w = fmaf(t, sinf(w.w), w.w);
            oo[base + j * 256] = w;
        }
    } else {
        // k in {0,1,2,3,5}: affine A*x + Bc
        float A = 1.f, Bc = 0.f;
        if      (k == 1) A = 1.f + t;
        else if (k == 2) Bc = t;
        else if (k == 3) A = 1.f - t;
        else if (k == 5) A = expf(-t);
        #pragma unroll
        for (int j = 0; j < 4; j++) {
            float4 w = v[j];
            w.x = fmaf(w.x, A, Bc); w.y = fmaf(w.y, A, Bc);
            w.z = fmaf(w.z, A, Bc); w.w = fmaf(w.w, A, Bc);
            oo[base + j * 256] = w;
        }
    }
}

extern "C" void kernel_launch(void* const* d_in, const int* in_sizes, int n_in,
                              void* d_out, int out_size)
{
    const float* x         = (const float*)d_in[0];
    const float* prev_prob = (const float*)d_in[1];
    const float* features  = (const float*)d_in[2];
    const float* gumbel    = (const float*)d_in[3];
    // d_in[4] = log_temperature: dead for forward values (exact one-hot selection;
    // tau>0 never changes the argmax; prob uses the raw softmax of logits).
    const float* pW1 = (const float*)d_in[5];
    const float* pb1 = (const float*)d_in[6];
    const float* pW2 = (const float*)d_in[7];
    const float* pb2 = (const float*)d_in[8];
    const float* pW3 = (const float*)d_in[9];
    const float* pb3 = (const float*)d_in[10];
    const float* iW1 = (const float*)d_in[11];
    const float* ib1 = (const float*)d_in[12];
    const float* iW2 = (const float*)d_in[13];
    const float* ib2 = (const float*)d_in[14];
    const float* iW3 = (const float*)d_in[15];
    const float* ib3 = (const float*)d_in[16];

    float* out      = (float*)d_out;
    float* out_prob = out + XAUG_ELEMS;              // (B,K)
    float* out_int  = out_prob + BB * KK;            // (B,K)
    float* out_sel  = out_int  + BB * KK;            // (B,)

    setup_kernel<<<BB, HH>>>(prev_prob, features, gumbel,
                             pW1, pb1, pW2, pb2, pW3, pb3,
                             iW1, ib1, iW2, ib2, iW3, ib3,
                             out_prob, out_int, out_sel);

    // Apply kernel with Programmatic Dependent Launch: it may begin (and issue
    // its x loads) while setup drains; it synchronizes before reading g_sel.
    cudaLaunchConfig_t cfg = {};
    cfg.gridDim  = dim3(32, BB, 1);
    cfg.blockDim = dim3(256, 1, 1);
    cfg.dynamicSmemBytes = 0;
    cfg.stream = 0;
    cudaLaunchAttribute attr[1];
    attr[0].id = cudaLaunchAttributeProgrammaticStreamSerialization;
    attr[0].val.programmaticStreamSerializationAllowed = 1;
    cfg.attrs = attr;
    cfg.numAttrs = 1;
    cudaLaunchKernelEx(&cfg, apply_kernel, x, out);
}

// round 8
// speedup vs baseline: 1.4063x; 1.1680x over previous
#include <cuda_runtime.h>
#include <cuda_bf16.h>
#include <math.h>

// Problem dims (fixed by setup_inputs)
#define BB 64
#define KK 8
#define FF 24
#define DD 32   // KK + FF
#define HH 64
#define LL 2048
#define CC 64
#define XAUG_ELEMS (BB * LL * CC)   // 8388608

// Per-batch selected transform + its intensity (scratch; no allocation allowed)
__device__ int   g_sel_k[BB];
__device__ float g_sel_t[BB];

// ---------------------------------------------------------------------------
// Kernel 1: per-batch MLPs, softmax, argmax(logits+gumbel). One block per
// batch, 128 threads: prob MLP on threads 0-63, intensity MLP on 64-127,
// running CONCURRENTLY (halves the serial chain vs sequential MLPs).
// Triggers the dependent apply kernel via PDL when done.
// ---------------------------------------------------------------------------
__global__ void __launch_bounds__(128) setup_kernel(
    const float* __restrict__ prev_prob,   // (B,K)
    const float* __restrict__ features,    // (B,F)
    const float* __restrict__ gumbel,      // (B,K)
    const float* __restrict__ pW1, const float* __restrict__ pb1,
    const float* __restrict__ pW2, const float* __restrict__ pb2,
    const float* __restrict__ pW3, const float* __restrict__ pb3,
    const float* __restrict__ iW1, const float* __restrict__ ib1,
    const float* __restrict__ iW2, const float* __restrict__ ib2,
    const float* __restrict__ iW3, const float* __restrict__ ib3,
    float* __restrict__ out_prob,          // (B,K)
    float* __restrict__ out_int,           // (B,K)
    float* __restrict__ out_sel)           // (B,)
{
    const int b   = blockIdx.x;
    const int tid = threadIdx.x;           // 0..127
    const int lt  = tid & 63;
    const bool isP = (tid < 64);

    __shared__ float s_in[DD];
    __shared__ float hp1[HH], hp2[HH];     // prob hiddens
    __shared__ float hi1[HH], hi2[HH];     // intensity hiddens
    __shared__ float s_logit[KK];
    __shared__ float s_int[KK];

    if (tid < KK)       s_in[tid] = prev_prob[b * KK + tid];
    else if (tid < DD)  s_in[tid] = features[b * FF + (tid - KK)];
    __syncthreads();

    // ---- layer 1 (both MLPs in parallel) ----
    {
        const float* W1 = isP ? pW1 : iW1;  const float* b1 = isP ? pb1 : ib1;
        float a = b1[lt];
        #pragma unroll
        for (int i = 0; i < DD; i++) a = fmaf(s_in[i], W1[i * HH + lt], a);
        (isP ? hp1 : hi1)[lt] = fmaxf(a, 0.f);
    }
    __syncthreads();
    // ---- layer 2 ----
    {
        const float* W2 = isP ? pW2 : iW2;  const float* b2 = isP ? pb2 : ib2;
        const float* h1 = isP ? hp1 : hi1;
        float a = b2[lt];
        #pragma unroll 16
        for (int i = 0; i < HH; i++) a = fmaf(h1[i], W2[i * HH + lt], a);
        (isP ? hp2 : hi2)[lt] = fmaxf(a, 0.f);
    }
    __syncthreads();
    // ---- layer 3 ----
    if (lt < KK) {
        const float* W3 = isP ? pW3 : iW3;  const float* b3 = isP ? pb3 : ib3;
        const float* h2 = isP ? hp2 : hi2;
        float a = b3[lt];
        #pragma unroll 16
        for (int i = 0; i < HH; i++) a = fmaf(h2[i], W3[i * KK + lt], a);
        if (isP) s_logit[lt] = a;
        else     s_int[lt]   = (a > 20.f) ? a : log1pf(expf(a));  // stable softplus
    }
    __syncthreads();

    if (tid == 0) {
        // softmax over K=8 logits
        float m = s_logit[0];
        #pragma unroll
        for (int k = 1; k < KK; k++) m = fmaxf(m, s_logit[k]);
        float e[KK]; float sum = 0.f;
        #pragma unroll
        for (int k = 0; k < KK; k++) { e[k] = expf(s_logit[k] - m); sum += e[k]; }
        float inv = 1.f / sum;
        #pragma unroll
        for (int k = 0; k < KK; k++) out_prob[b * KK + k] = e[k] * inv;

        // argmax(logits + gumbel) == argmax(y_soft); selection is exactly one-hot
        // (y_hard + y_soft - stop_grad(y_soft) == y_hard numerically).
        int best = 0;
        float bv = s_logit[0] + gumbel[b * KK + 0];
        #pragma unroll
        for (int k = 1; k < KK; k++) {
            float v = s_logit[k] + gumbel[b * KK + k];
            if (v > bv) { bv = v; best = k; }
        }
        #pragma unroll
        for (int k = 0; k < KK; k++) out_int[b * KK + k] = s_int[k];
        out_sel[b] = (float)best;
        g_sel_k[b] = best;
        g_sel_t[b] = s_int[best];
    }
    __syncthreads();
#if __CUDA_ARCH__ >= 900
    // Release the dependent apply kernel; this CTA's prior writes become
    // visible to it after its cudaGridDependencySynchronize().
    cudaTriggerProgrammaticLaunchCompletion();
#endif
}

// ---------------------------------------------------------------------------
// Kernel 2: apply the single selected transform per batch.
// MAX-OCCUPANCY shape: ITERS=2 (8 data regs -> ~28 regs total -> 8 blocks/SM
// = 100% occupancy). grid = (64, B), 256 threads, 2 float4 per thread.
// Loads are k-independent (k==7 flip applied on the store side) and issued
// before the PDL wait.
// ---------------------------------------------------------------------------
__global__ void __launch_bounds__(256) apply_kernel(
    const float* __restrict__ x, float* __restrict__ out)
{
    const int b = blockIdx.y;

    const float4* __restrict__ xi = (const float4*)(x   + (size_t)b * LL * CC);
    float4*       __restrict__ oo = (float4*)      (out + (size_t)b * LL * CC);

    const int base = blockIdx.x * 512 + threadIdx.x;   // 64 blocks * 512 = 32768

    // k-independent loads, issued before the dependency wait
    float4 v0 = xi[base];
    float4 v1 = xi[base + 256];

#if __CUDA_ARCH__ >= 900
    cudaGridDependencySynchronize();   // wait for setup; makes g_sel visible
#endif
    const int   k = g_sel_k[b];
    const float t = g_sel_t[b];

    if (k == 7) {
        // time reversal: identity values, flipped (still coalesced) store position
        int i0 = base, i1 = base + 256;
        oo[((LL - 1 - (i0 >> 4)) << 4) + (i0 & 15)] = v0;
        oo[((LL - 1 - (i1 >> 4)) << 4) + (i1 & 15)] = v1;
    } else if (k == 4) {
        const float A = 1.f + t;
        v0.x = tanhf(v0.x * A); v0.y = tanhf(v0.y * A);
        v0.z = tanhf(v0.z * A); v0.w = tanhf(v0.w * A);
        v1.x = tanhf(v1.x * A); v1.y = tanhf(v1.y * A);
        v1.z = tanhf(v1.z * A); v1.w = tanhf(v1.w * A);
        oo[base] = v0; oo[base + 256] = v1;
    } else if (k == 6) {
        v0.x = fmaf(t, sinf(v0.x), v0.x); v0.y = fmaf(t, sinf(v0.y), v0.y);
        v0.z = fmaf(t, sinf(v0.z), v0.z); v0.w = fmaf(t, sinf(v0.w), v0.w);
        v1.x = fmaf(t, sinf(v1.x), v1.x); v1.y = fmaf(t, sinf(v1.y), v1.y);
        v1.z = fmaf(t, sinf(v1.z), v1.z); v1.w = fmaf(t, sinf(v1.w), v1.w);
        oo[base] = v0; oo[base + 256] = v1;
    } else {
        // k in {0,1,2,3,5}: affine A*x + Bc
        float A = 1.f, Bc = 0.f;
        if      (k == 1) A = 1.f + t;
        else if (k == 2) Bc = t;
        else if (k == 3) A = 1.f - t;
        else if (k == 5) A = expf(-t);
        v0.x = fmaf(v0.x, A, Bc); v0.y = fmaf(v0.y, A, Bc);
        v0.z = fmaf(v0.z, A, Bc); v0.w = fmaf(v0.w, A, Bc);
        v1.x = fmaf(v1.x, A, Bc); v1.y = fmaf(v1.y, A, Bc);
        v1.z = fmaf(v1.z, A, Bc); v1.w = fmaf(v1.w, A, Bc);
        oo[base] = v0; oo[base + 256] = v1;
    }
}

extern "C" void kernel_launch(void* const* d_in, const int* in_sizes, int n_in,
                              void* d_out, int out_size)
{
    const float* x         = (const float*)d_in[0];
    const float* prev_prob = (const float*)d_in[1];
    const float* features  = (const float*)d_in[2];
    const float* gumbel    = (const float*)d_in[3];
    // d_in[4] = log_temperature: dead for forward values (exact one-hot selection;
    // tau>0 never changes the argmax; prob uses the raw softmax of logits).
    const float* pW1 = (const float*)d_in[5];
    const float* pb1 = (const float*)d_in[6];
    const float* pW2 = (const float*)d_in[7];
    const float* pb2 = (const float*)d_in[8];
    const float* pW3 = (const float*)d_in[9];
    const float* pb3 = (const float*)d_in[10];
    const float* iW1 = (const float*)d_in[11];
    const float* ib1 = (const float*)d_in[12];
    const float* iW2 = (const float*)d_in[13];
    const float* ib2 = (const float*)d_in[14];
    const float* iW3 = (const float*)d_in[15];
    const float* ib3 = (const float*)d_in[16];

    float* out      = (float*)d_out;
    float* out_prob = out + XAUG_ELEMS;              // (B,K)
    float* out_int  = out_prob + BB * KK;            // (B,K)
    float* out_sel  = out_int  + BB * KK;            // (B,)

    setup_kernel<<<BB, 128>>>(prev_prob, features, gumbel,
                              pW1, pb1, pW2, pb2, pW3, pb3,
                              iW1, ib1, iW2, ib2, iW3, ib3,
                              out_prob, out_int, out_sel);

    // Apply kernel with Programmatic Dependent Launch: begins (and issues
    // its x loads) while setup drains; synchronizes before reading g_sel.
    cudaLaunchConfig_t cfg = {};
    cfg.gridDim  = dim3(64, BB, 1);
    cfg.blockDim = dim3(256, 1, 1);
    cfg.dynamicSmemBytes = 0;
    cfg.stream = 0;
    cudaLaunchAttribute attr[1];
    attr[0].id = cudaLaunchAttributeProgrammaticStreamSerialization;
    attr[0].val.programmaticStreamSerializationAllowed = 1;
    cfg.attrs = attr;
    cfg.numAttrs = 1;
    cudaLaunchKernelEx(&cfg, apply_kernel, x, out);
}